// round 1
// baseline (speedup 1.0000x reference)
#include <cuda_runtime.h>

#define XSIZE 256
#define NB 128

__global__ __launch_bounds__(128) void qconv_kernel(const float* __restrict__ x,
                                                    const float* __restrict__ w,
                                                    float* __restrict__ out)
{
    const int j  = threadIdx.x;      // col block 0..127
    const int bi = blockIdx.x;       // b*128 + i
    const int i  = bi & (NB - 1);    // row block
    // patch angles: x[b, 2i, 2j], x[b, 2i, 2j+1], x[b, 2i+1, 2j], x[b, 2i+1, 2j+1]
    const size_t base = ((size_t)(bi >> 7) * XSIZE + 2 * i) * XSIZE + 2 * j;
    const float2 r0 = *reinterpret_cast<const float2*>(x + base);
    const float2 r1 = *reinterpret_cast<const float2*>(x + base + XSIZE);
    const float x0 = r0.x, x1 = r0.y, x2 = r1.x, x3 = r1.y;

    // RX coefficients from trainable weights (uniform across threads, L2-broadcast)
    float cw[4], sw[4];
#pragma unroll
    for (int q = 0; q < 4; q++) __sincosf(0.5f * __ldg(w + q), &sw[q], &cw[q]);

    const float S = x0 * x0 + x1 * x1 + x2 * x2 + x3 * x3;

    // diag_k = exp(i*phi_k), phi_k = 0.25*(S - t^2) - 0.5*t,  t_k = sum_q sign_q x_q
    // sign_q = +1 iff bit q of k set. t_{k^15} = -t_k -> 8 t values, 16 sincos.
    float vr[16], vi[16];
#pragma unroll
    for (int e = 0; e < 8; e++) {
        const float t = x3 + ((e & 4) ? x2 : -x2)
                           + ((e & 2) ? x1 : -x1)
                           + ((e & 1) ? x0 : -x0);
        const int k1 = 8 | e;        // bit3 = 1 (+x3)
        const int k0 = k1 ^ 15;      // complementary signs
        const float u  = 0.25f * (S - t * t);
        const float p1 = u - 0.5f * t;
        const float p0 = u + 0.5f * t;
        __sincosf(p1, &vi[k1], &vr[k1]);
        __sincosf(p0, &vi[k0], &vr[k0]);
    }

    // Apply RX(w_q) on qubit q (bit q): 4 butterfly layers.
    // a' = c*a - i s*b ; b' = -i s*a + c*b
#pragma unroll
    for (int q = 0; q < 4; q++) {
        const float c = cw[q], s = sw[q];
#pragma unroll
        for (int m = 0; m < 8; m++) {
            const int j0 = ((m >> q) << (q + 1)) | (m & ((1 << q) - 1));
            const int j1 = j0 | (1 << q);
            const float ar = vr[j0], ai = vi[j0];
            const float br = vr[j1], bim = vi[j1];
            vr[j0] = c * ar + s * bim;
            vi[j0] = c * ai - s * br;
            vr[j1] = c * br + s * ai;
            vi[j1] = c * bim - s * ar;
        }
    }

    // CNOT ring = permutation (linear over GF(2)); composed with the per-qubit
    // readout it reduces to parity-masked probability sums.
    float o0 = 0.f, o1 = 0.f, o2 = 0.f, o3 = 0.f;
#pragma unroll
    for (int k = 0; k < 16; k++) {
        const float p = vr[k] * vr[k] + vi[k] * vi[k];
        if (__popc(k & 0xF) & 1) o0 += p;
        if (__popc(k & 0x7) & 1) o1 += p;
        if (__popc(k & 0x3) & 1) o2 += p;
        if (__popc(k & 0xE) & 1) o3 += p;
    }

    // initial state factor 0.25 -> probs scale 1/16
    float4 o;
    o.x = 0.0625f * o0;
    o.y = 0.0625f * o1;
    o.z = 0.0625f * o2;
    o.w = 0.0625f * o3;
    reinterpret_cast<float4*>(out)[(size_t)bi * NB + j] = o;
}

extern "C" void kernel_launch(void* const* d_in, const int* in_sizes, int n_in,
                              void* d_out, int out_size)
{
    const float* x = (const float*)d_in[0];
    const float* w = (const float*)d_in[1];
    float* out = (float*)d_out;
    const int batch = in_sizes[0] / (XSIZE * XSIZE);
    qconv_kernel<<<batch * NB, NB>>>(x, w, out);
}

// round 2
// speedup vs baseline: 1.1214x; 1.1214x over previous
#include <cuda_runtime.h>

typedef unsigned long long u64;
#define XSIZE 256

__device__ __forceinline__ u64 pk(float lo, float hi) {
    u64 r; asm("mov.b64 %0,{%1,%2};" : "=l"(r) : "f"(lo), "f"(hi)); return r;
}
__device__ __forceinline__ void upk(float& lo, float& hi, u64 v) {
    asm("mov.b64 {%0,%1},%2;" : "=f"(lo), "=f"(hi) : "l"(v));
}
__device__ __forceinline__ u64 fma2(u64 a, u64 b, u64 c) {
    u64 d; asm("fma.rn.f32x2 %0,%1,%2,%3;" : "=l"(d) : "l"(a), "l"(b), "l"(c)); return d;
}
__device__ __forceinline__ u64 mul2(u64 a, u64 b) {
    u64 d; asm("mul.rn.f32x2 %0,%1,%2;" : "=l"(d) : "l"(a), "l"(b)); return d;
}
__device__ __forceinline__ u64 add2(u64 a, u64 b) {
    u64 d; asm("add.rn.f32x2 %0,%1,%2;" : "=l"(d) : "l"(a), "l"(b)); return d;
}
__device__ __forceinline__ u64 neg2(u64 a) { return a ^ 0x8000000080000000ULL; }

// 64 threads/block; each thread packs TWO adjacent patches (j=2t, 2t+1) into f32x2 lanes.
__global__ __launch_bounds__(64) void qconv_kernel2(const float* __restrict__ x,
                                                    const float* __restrict__ w,
                                                    float* __restrict__ out)
{
    const int tid = threadIdx.x;         // 0..63 -> patch pair
    const int bi  = blockIdx.x;          // b*128 + i
    const int i   = bi & 127;
    const size_t base = ((size_t)(bi >> 7) * XSIZE + 2 * i) * XSIZE + 4 * tid;
    const float4 r0 = *reinterpret_cast<const float4*>(x + base);
    const float4 r1 = *reinterpret_cast<const float4*>(x + base + XSIZE);
    // lane0 = patch A (r0.x r0.y r1.x r1.y), lane1 = patch B (r0.z r0.w r1.z r1.w)
    const u64 X0 = pk(r0.x, r0.z);
    const u64 X1 = pk(r0.y, r0.w);
    const u64 X2 = pk(r1.x, r1.z);
    const u64 X3 = pk(r1.y, r1.w);

    // RX coefficients (uniform)
    u64 CW[4], SW[4], NSW[4];
#pragma unroll
    for (int q = 0; q < 4; q++) {
        float cq, sq;
        __sincosf(0.5f * __ldg(w + q), &sq, &cq);
        CW[q] = pk(cq, cq); SW[q] = pk(sq, sq); NSW[q] = neg2(SW[q]);
    }

    const u64 S  = fma2(X0, X0, fma2(X1, X1, fma2(X2, X2, mul2(X3, X3))));
    const u64 S4 = mul2(S, pk(0.25f, 0.25f));
    const u64 NQ = pk(-0.25f, -0.25f);
    const u64 NH = pk(-0.5f, -0.5f);
    const u64 PH = pk(0.5f, 0.5f);
    const u64 nX0 = neg2(X0), nX1 = neg2(X1), nX2 = neg2(X2);

    // diag_k = exp(i*phi_k), phi = 0.25*(S - t^2) -/+ 0.5*t, t_{k^15} = -t_k
    u64 vr[16], vi[16];
#pragma unroll
    for (int e = 0; e < 8; e++) {
        const u64 t = add2(add2(X3, (e & 4) ? X2 : nX2),
                           add2((e & 2) ? X1 : nX1, (e & 1) ? X0 : nX0));
        const int k1 = 8 | e;
        const int k0 = k1 ^ 15;
        const u64 u  = fma2(mul2(t, NQ), t, S4);
        const u64 p1 = fma2(t, NH, u);
        const u64 p0 = fma2(t, PH, u);
        float plo, phi_, slo, clo, shi, chi;
        upk(plo, phi_, p1);
        __sincosf(plo, &slo, &clo);
        __sincosf(phi_, &shi, &chi);
        vi[k1] = pk(slo, shi); vr[k1] = pk(clo, chi);
        upk(plo, phi_, p0);
        __sincosf(plo, &slo, &clo);
        __sincosf(phi_, &shi, &chi);
        vi[k0] = pk(slo, shi); vr[k0] = pk(clo, chi);
    }

    // RX butterflies on qubits 0..3:  a' = c a - i s b ; b' = -i s a + c b
#pragma unroll
    for (int q = 0; q < 4; q++) {
        const u64 c = CW[q], s = SW[q], ns = NSW[q];
#pragma unroll
        for (int m = 0; m < 8; m++) {
            const int j0 = ((m >> q) << (q + 1)) | (m & ((1 << q) - 1));
            const int j1 = j0 | (1 << q);
            const u64 ar = vr[j0], ai = vi[j0];
            const u64 br = vr[j1], bim = vi[j1];
            vr[j0] = fma2(c, ar, mul2(s, bim));
            vi[j0] = fma2(c, ai, mul2(ns, br));
            vr[j1] = fma2(c, br, mul2(s, ai));
            vi[j1] = fma2(c, bim, mul2(ns, ar));
        }
    }

    // CNOT ring + Z readout = parity-masked probability sums
    u64 o0 = 0ULL, o1 = 0ULL, o2 = 0ULL, o3 = 0ULL;
#pragma unroll
    for (int k = 0; k < 16; k++) {
        const u64 p = fma2(vr[k], vr[k], mul2(vi[k], vi[k]));
        if (__popc(k & 0xF) & 1) o0 = add2(o0, p);
        if (__popc(k & 0x7) & 1) o1 = add2(o1, p);
        if (__popc(k & 0x3) & 1) o2 = add2(o2, p);
        if (__popc(k & 0xE) & 1) o3 = add2(o3, p);
    }

    const u64 SC = pk(0.0625f, 0.0625f);
    float4 oa, ob;
    upk(oa.x, ob.x, mul2(o0, SC));
    upk(oa.y, ob.y, mul2(o1, SC));
    upk(oa.z, ob.z, mul2(o2, SC));
    upk(oa.w, ob.w, mul2(o3, SC));

    float* dst = out + (size_t)bi * 512 + 8 * tid;
    reinterpret_cast<float4*>(dst)[0] = oa;
    reinterpret_cast<float4*>(dst)[1] = ob;
}

extern "C" void kernel_launch(void* const* d_in, const int* in_sizes, int n_in,
                              void* d_out, int out_size)
{
    const float* x = (const float*)d_in[0];
    const float* w = (const float*)d_in[1];
    float* out = (float*)d_out;
    const int batch = in_sizes[0] / (XSIZE * XSIZE);
    qconv_kernel2<<<batch * 128, 64>>>(x, w, out);
}